// round 5
// baseline (speedup 1.0000x reference)
#include <cuda_runtime.h>
#include <math.h>

// Problem constants
#define N_CLASS 32000
#define EMB     256
#define HID     512
#define BATCH   256
#define SEQ     64
#define G4      2048            // 4 gates * HID
#define MB_     (SEQ*BATCH)     // 16384
#define BH      (BATCH*HID)     // 131072

// ---------------- static device scratch (allocation-free) ----------------
__device__ float g_emb  [MB_*EMB];        //  16 MB  gathered embeddings [s*B+b][e]
__device__ float g_gin  [MB_*G4];         // 134 MB  precomputed input-gate terms [s*B+b][n]
__device__ float g_h0all[MB_*HID];        //  33 MB  layer-0 h for every step
__device__ float g_h    [2*BH];           //  h double buffer
__device__ float g_c    [BH];             //  c (in-place)
__device__ float g_gates[BATCH*G4];       //  per-step gate pre-activations
__device__ float g_wicat[G4*EMB];         //  concat input weights  [n][e]   (i,f,g,o)
__device__ float g_whcat[G4*HID];         //  concat hidden weights [n][k]
__device__ float g_bcat [G4];             //  concat biases
__device__ float g_weff [G4*HID];         //  folded layer-1 input weights: Wicat @ W
__device__ float g_beff [G4];             //  folded layer-1 bias: Wicat @ b + bcat

__device__ __forceinline__ float sigmoidf_(float x) { return 1.0f / (1.0f + expf(-x)); }

// ------------- build concatenated weight/bias matrices (i,f,g,o) -------------
__global__ void __launch_bounds__(256) prep_concat_kernel(
    const float* __restrict__ Wii, const float* __restrict__ Whi, const float* __restrict__ bi,
    const float* __restrict__ Wif, const float* __restrict__ Whf, const float* __restrict__ bf,
    const float* __restrict__ Wig, const float* __restrict__ Whg, const float* __restrict__ bg,
    const float* __restrict__ Wio, const float* __restrict__ Who, const float* __restrict__ bo)
{
    int idx = blockIdx.x * 256 + threadIdx.x;
    if (idx >= G4 * HID) return;
    int n = idx / HID;
    int k = idx - n * HID;
    int g = n >> 9;        // gate index 0..3
    int u = n & 511;       // hidden unit
    const float* Wh = (g == 0) ? Whi : (g == 1) ? Whf : (g == 2) ? Whg : Who;
    g_whcat[idx] = Wh[u * HID + k];
    if (k < EMB) {
        const float* Wi = (g == 0) ? Wii : (g == 1) ? Wif : (g == 2) ? Wig : Wio;
        g_wicat[n * EMB + k] = Wi[u * EMB + k];
    }
    if (k == 0) {
        const float* bv = (g == 0) ? bi : (g == 1) ? bf : (g == 2) ? bg : bo;
        g_bcat[n] = bv[u];
    }
}

// ------------- embedding gather: Emb[s*B+b][e] = C[X[b][s]][e] -------------
__global__ void __launch_bounds__(EMB) embed_kernel(const int* __restrict__ X,
                                                    const float* __restrict__ C)
{
    int sb = blockIdx.x;          // s*BATCH + b
    int s  = sb >> 8;             // BATCH == 256
    int b  = sb & 255;
    int row = X[b * SEQ + s];
    g_emb[(size_t)sb * EMB + threadIdx.x] = C[(size_t)row * EMB + threadIdx.x];
}

// ------------- generic SGEMM: Y[m][n] = (bias?bias[n]:0) + (Cin?Cin[m][n]:0)
//                                      + sum_k A[m][k] * B(n,k)
// B(n,k) = B[n*K + k] normally, or B[k*N + n] if TRANSB.
// Requires M%64==0, N%64==0, K%16==0 (true for all our shapes). -------------
template <bool TRANSB>
__global__ void __launch_bounds__(256) gemm64_kernel(
    const float* __restrict__ A, const float* __restrict__ B,
    const float* __restrict__ bias, const float* __restrict__ Cin,
    float* __restrict__ Y, int M, int N, int K)
{
    const int BM = 64, BN = 64, BK = 16;
    __shared__ float As[BK][BM];
    __shared__ float Bs[BK][BN];

    int bm = blockIdx.y * BM;
    int bn = blockIdx.x * BN;
    int tid = threadIdx.x;
    int tx = tid & 15;      // n direction (16 groups of 4)
    int ty = tid >> 4;      // m direction (16 groups of 4)

    float acc[4][4];
#pragma unroll
    for (int i = 0; i < 4; i++)
#pragma unroll
        for (int j = 0; j < 4; j++) acc[i][j] = 0.0f;

    for (int k0 = 0; k0 < K; k0 += BK) {
#pragma unroll
        for (int i = tid; i < BM * BK; i += 256) {
            int m = i >> 4, k = i & 15;
            As[k][m] = A[(size_t)(bm + m) * K + (k0 + k)];
        }
        if (!TRANSB) {
#pragma unroll
            for (int i = tid; i < BN * BK; i += 256) {
                int n = i >> 4, k = i & 15;
                Bs[k][n] = B[(size_t)(bn + n) * K + (k0 + k)];
            }
        } else {
#pragma unroll
            for (int i = tid; i < BN * BK; i += 256) {
                int k = i >> 6, n = i & 63;
                Bs[k][n] = B[(size_t)(k0 + k) * N + (bn + n)];
            }
        }
        __syncthreads();

#pragma unroll
        for (int k = 0; k < BK; k++) {
            float4 av = *(const float4*)&As[k][ty * 4];
            float4 bv = *(const float4*)&Bs[k][tx * 4];
            float a[4] = {av.x, av.y, av.z, av.w};
            float b[4] = {bv.x, bv.y, bv.z, bv.w};
#pragma unroll
            for (int i = 0; i < 4; i++)
#pragma unroll
                for (int j = 0; j < 4; j++) acc[i][j] += a[i] * b[j];
        }
        __syncthreads();
    }

#pragma unroll
    for (int i = 0; i < 4; i++) {
        int m = bm + ty * 4 + i;
        int n = bn + tx * 4;
        float4 v;
        v.x = acc[i][0]; v.y = acc[i][1]; v.z = acc[i][2]; v.w = acc[i][3];
        if (bias) {
            v.x += bias[n + 0]; v.y += bias[n + 1];
            v.z += bias[n + 2]; v.w += bias[n + 3];
        }
        if (Cin) {
            float4 cv = *(const float4*)&Cin[(size_t)m * N + n];
            v.x += cv.x; v.y += cv.y; v.z += cv.z; v.w += cv.w;
        }
        *(float4*)&Y[(size_t)m * N + n] = v;
    }
}

// ------------- beff[n] = bcat[n] + sum_e Wicat[n][e] * b_proj[e] -------------
__global__ void __launch_bounds__(256) beff_kernel(const float* __restrict__ bproj)
{
    int n = blockIdx.x * 256 + threadIdx.x;
    if (n >= G4) return;
    float s = g_bcat[n];
    const float* w = &g_wicat[n * EMB];
    for (int e = 0; e < EMB; e++) s += w[e] * bproj[e];
    g_beff[n] = s;
}

// ------------- zero h buffer 0 and c -------------
__global__ void __launch_bounds__(256) zero_hc_kernel()
{
    int i = blockIdx.x * 256 + threadIdx.x;
    if (i < BH) { g_h[i] = 0.0f; g_c[i] = 0.0f; }
}

// ------------- LSTM elementwise: consume g_gates, update c and h -------------
__global__ void __launch_bounds__(256) lstm_elem_kernel(int s, int store_all)
{
    int idx = blockIdx.x * 256 + threadIdx.x;
    if (idx >= BH) return;
    int b = idx >> 9;           // HID == 512
    int u = idx & 511;
    const float* Yr = &g_gates[(size_t)b * G4];
    float iv = sigmoidf_(Yr[u]);
    float fv = sigmoidf_(Yr[HID + u]);
    float gv = tanhf(Yr[2 * HID + u]);
    float ov = sigmoidf_(Yr[3 * HID + u]);
    float cn = fv * g_c[idx] + iv * gv;
    float hn = ov * tanhf(cn);
    g_c[idx] = cn;
    g_h[((s + 1) & 1) * BH + idx] = hn;
    if (store_all) g_h0all[(size_t)s * BH + idx] = hn;
}

// =============================== launch ===============================
extern "C" void kernel_launch(void* const* d_in, const int* in_sizes, int n_in,
                              void* d_out, int out_size)
{
    const int*   X    = (const int*)  d_in[0];
    const float* C    = (const float*)d_in[1];
    const float* Wii  = (const float*)d_in[2];
    const float* Whi  = (const float*)d_in[3];
    const float* bi   = (const float*)d_in[4];
    const float* Wif  = (const float*)d_in[5];
    const float* Whf  = (const float*)d_in[6];
    const float* bf   = (const float*)d_in[7];
    const float* Wig  = (const float*)d_in[8];
    const float* Whg  = (const float*)d_in[9];
    const float* bg   = (const float*)d_in[10];
    const float* Wio  = (const float*)d_in[11];
    const float* Who  = (const float*)d_in[12];
    const float* bo   = (const float*)d_in[13];
    const float* Wp   = (const float*)d_in[14];   // [EMB, HID]
    const float* bp   = (const float*)d_in[15];   // [EMB]
    const float* Wfin = (const float*)d_in[16];   // [N_CLASS, HID]
    const float* bfin = (const float*)d_in[17];   // [N_CLASS]
    float* out = (float*)d_out;

    float *p_emb, *p_gin, *p_h0all, *p_h, *p_whcat, *p_wicat, *p_bcat,
          *p_weff, *p_beff, *p_gates;
    cudaGetSymbolAddress((void**)&p_emb,   g_emb);
    cudaGetSymbolAddress((void**)&p_gin,   g_gin);
    cudaGetSymbolAddress((void**)&p_h0all, g_h0all);
    cudaGetSymbolAddress((void**)&p_h,     g_h);
    cudaGetSymbolAddress((void**)&p_whcat, g_whcat);
    cudaGetSymbolAddress((void**)&p_wicat, g_wicat);
    cudaGetSymbolAddress((void**)&p_bcat,  g_bcat);
    cudaGetSymbolAddress((void**)&p_weff,  g_weff);
    cudaGetSymbolAddress((void**)&p_beff,  g_beff);
    cudaGetSymbolAddress((void**)&p_gates, g_gates);

    // 1) concat weights/biases
    prep_concat_kernel<<<(G4 * HID) / 256, 256>>>(Wii, Whi, bi, Wif, Whf, bf,
                                                  Wig, Whg, bg, Wio, Who, bo);
    // 2) embedding gather
    embed_kernel<<<MB_, EMB>>>(X, C);

    // 3) Gin0 = Emb @ Wicat^T + bcat        [16384 x 2048], K=256
    gemm64_kernel<false><<<dim3(G4 / 64, MB_ / 64), 256>>>(
        p_emb, p_wicat, p_bcat, nullptr, p_gin, MB_, G4, EMB);

    // 4) fold projection into layer-1 input weights:
    //    Weff[n][k] = sum_e Wicat[n][e] * Wp[e][k]   (TRANSB: Wp is [EMB][HID])
    gemm64_kernel<true><<<dim3(HID / 64, G4 / 64), 256>>>(
        p_wicat, Wp, nullptr, nullptr, p_weff, G4, HID, EMB);
    beff_kernel<<<G4 / 256, 256>>>(bp);

    // 5) layer-0 recurrence (store h0 for every step)
    zero_hc_kernel<<<BH / 256, 256>>>();
    for (int s = 0; s < SEQ; s++) {
        gemm64_kernel<false><<<dim3(G4 / 64, BATCH / 64), 256>>>(
            p_h + (s & 1) * BH, p_whcat, nullptr,
            p_gin + (size_t)s * BATCH * G4, p_gates, BATCH, G4, HID);
        lstm_elem_kernel<<<BH / 256, 256>>>(s, 1);
    }

    // 6) Gin1 = H0all @ Weff^T + beff       [16384 x 2048], K=512
    gemm64_kernel<false><<<dim3(G4 / 64, MB_ / 64), 256>>>(
        p_h0all, p_weff, p_beff, nullptr, p_gin, MB_, G4, HID);

    // 7) layer-1 recurrence
    zero_hc_kernel<<<BH / 256, 256>>>();
    for (int s = 0; s < SEQ; s++) {
        gemm64_kernel<false><<<dim3(G4 / 64, BATCH / 64), 256>>>(
            p_h + (s & 1) * BH, p_whcat, nullptr,
            p_gin + (size_t)s * BATCH * G4, p_gates, BATCH, G4, HID);
        lstm_elem_kernel<<<BH / 256, 256>>>(s, 0);
    }

    // 8) logits = h_last @ Wfin^T + bfin    [256 x 32000], K=512
    //    (SEQ is even, so final h lives in buffer 0 == p_h)
    gemm64_kernel<false><<<dim3(N_CLASS / 64, BATCH / 64), 256>>>(
        p_h, Wfin, bfin, nullptr, out, BATCH, N_CLASS, HID);
}

// round 6
// speedup vs baseline: 1.1891x; 1.1891x over previous
#include <cuda_runtime.h>
#include <math.h>

// Problem constants
#define N_CLASS 32000
#define EMB     256
#define HID     512
#define BATCH   256
#define SEQ     64
#define G4      2048            // 4 gates * HID (gate-interleaved: n = u*4 + g)
#define MB_     (SEQ*BATCH)     // 16384
#define BH      (BATCH*HID)     // 131072

typedef unsigned long long u64;

// ---------------- static device scratch (allocation-free) ----------------
__device__ float g_emb  [MB_*EMB];        //  16 MB  gathered embeddings
__device__ float g_gin  [MB_*G4];         // 134 MB  input-gate terms (interleaved n)
__device__ float g_h0all[MB_*HID];        //  33 MB  layer-0 h for every step
__device__ float g_h    [2*BH];           //  h double buffer
__device__ float g_c    [BH];             //  c (in-place)
__device__ float g_wicat[G4*EMB];         //  interleaved input weights  [n][e]
__device__ float g_whq  [G4*HID];         //  interleaved hidden weights [n][k]
__device__ float g_bcat [G4];             //  interleaved biases
__device__ float g_weff [G4*HID];         //  folded layer-1 input weights
__device__ float g_beff [G4];             //  folded layer-1 bias

// ---------------- f32x2 packed math helpers ----------------
__device__ __forceinline__ u64 pack2(float x, float y) {
    u64 r; asm("mov.b64 %0, {%1, %2};" : "=l"(r) : "f"(x), "f"(y)); return r;
}
__device__ __forceinline__ float2 unpack2(u64 v) {
    float2 r; asm("mov.b64 {%0, %1}, %2;" : "=f"(r.x), "=f"(r.y) : "l"(v)); return r;
}
__device__ __forceinline__ void fma2(u64& d, u64 a, u64 b) {
    asm("fma.rn.f32x2 %0, %1, %2, %3;" : "=l"(d) : "l"(a), "l"(b), "l"(d));
}
__device__ __forceinline__ float sigmoidf_(float x) { return 1.0f / (1.0f + expf(-x)); }

// ------------- build gate-interleaved weight/bias matrices -------------
// n = u*4 + g, gate order g: 0=i, 1=f, 2=g, 3=o
__global__ void __launch_bounds__(256) prep_concat_kernel(
    const float* __restrict__ Wii, const float* __restrict__ Whi, const float* __restrict__ bi,
    const float* __restrict__ Wif, const float* __restrict__ Whf, const float* __restrict__ bf,
    const float* __restrict__ Wig, const float* __restrict__ Whg, const float* __restrict__ bg,
    const float* __restrict__ Wio, const float* __restrict__ Who, const float* __restrict__ bo)
{
    int idx = blockIdx.x * 256 + threadIdx.x;
    if (idx >= G4 * HID) return;
    int n = idx / HID;
    int k = idx - n * HID;
    int u = n >> 2;        // hidden unit
    int g = n & 3;         // gate
    const float* Wh = (g == 0) ? Whi : (g == 1) ? Whf : (g == 2) ? Whg : Who;
    g_whq[idx] = Wh[u * HID + k];
    if (k < EMB) {
        const float* Wi = (g == 0) ? Wii : (g == 1) ? Wif : (g == 2) ? Wig : Wio;
        g_wicat[n * EMB + k] = Wi[u * EMB + k];
    }
    if (k == 0) {
        const float* bv = (g == 0) ? bi : (g == 1) ? bf : (g == 2) ? bg : bo;
        g_bcat[n] = bv[u];
    }
}

// ------------- embedding gather -------------
__global__ void __launch_bounds__(EMB) embed_kernel(const int* __restrict__ X,
                                                    const float* __restrict__ C)
{
    int sb = blockIdx.x;          // s*BATCH + b
    int s  = sb >> 8;
    int b  = sb & 255;
    int row = X[b * SEQ + s];
    g_emb[(size_t)sb * EMB + threadIdx.x] = C[(size_t)row * EMB + threadIdx.x];
}

// ------------- 128x128x16 SGEMM, f32x2 packed FMA -------------
// Y[m][n] = (bias?bias[n]:0) + sum_k A[m][k] * B(n,k)
// B(n,k) = B[n*K+k] normally, B[k*N+n] if TRANSB.
// Requires M%128==0, N%128==0, K%16==0.
template <bool TRANSB>
__global__ void __launch_bounds__(256) gemm128_kernel(
    const float* __restrict__ A, const float* __restrict__ B,
    const float* __restrict__ bias, float* __restrict__ Y,
    int M, int N, int K)
{
    const int BM = 128, BN = 128, BK = 16;
    __shared__ float As[BK][BM];
    __shared__ float Bs[BK][BN];

    int bm = blockIdx.y * BM;
    int bn = blockIdx.x * BN;
    int tid = threadIdx.x;
    int tx = tid & 15;          // n group  (8 n each)
    int ty = tid >> 4;          // m group  (8 m each)
    int m0 = ty * 8;
    int n0 = tx * 8;

    u64 acc[8][4];
#pragma unroll
    for (int i = 0; i < 8; i++)
#pragma unroll
        for (int j = 0; j < 4; j++) acc[i][j] = 0ULL;

    for (int k0 = 0; k0 < K; k0 += BK) {
        // load A tile (transpose to As[k][m])
#pragma unroll
        for (int l = tid; l < 512; l += 256) {
            int r = l >> 2, kq = l & 3;
            float4 v = *(const float4*)&A[(size_t)(bm + r) * K + k0 + kq * 4];
            As[kq * 4 + 0][r] = v.x; As[kq * 4 + 1][r] = v.y;
            As[kq * 4 + 2][r] = v.z; As[kq * 4 + 3][r] = v.w;
        }
        if (!TRANSB) {
#pragma unroll
            for (int l = tid; l < 512; l += 256) {
                int r = l >> 2, kq = l & 3;
                float4 v = *(const float4*)&B[(size_t)(bn + r) * K + k0 + kq * 4];
                Bs[kq * 4 + 0][r] = v.x; Bs[kq * 4 + 1][r] = v.y;
                Bs[kq * 4 + 2][r] = v.z; Bs[kq * 4 + 3][r] = v.w;
            }
        } else {
#pragma unroll
            for (int l = tid; l < 512; l += 256) {
                int k = l >> 5, nq = l & 31;
                *(float4*)&Bs[k][nq * 4] =
                    *(const float4*)&B[(size_t)(k0 + k) * N + bn + nq * 4];
            }
        }
        __syncthreads();

#pragma unroll
        for (int k = 0; k < BK; k++) {
            float4 av0 = *(const float4*)&As[k][m0];
            float4 av1 = *(const float4*)&As[k][m0 + 4];
            u64 bp[4];
            bp[0] = *(const u64*)&Bs[k][n0];
            bp[1] = *(const u64*)&Bs[k][n0 + 2];
            bp[2] = *(const u64*)&Bs[k][n0 + 4];
            bp[3] = *(const u64*)&Bs[k][n0 + 6];
            float am[8] = {av0.x, av0.y, av0.z, av0.w, av1.x, av1.y, av1.z, av1.w};
#pragma unroll
            for (int i = 0; i < 8; i++) {
                u64 ad = pack2(am[i], am[i]);
#pragma unroll
                for (int j = 0; j < 4; j++) fma2(acc[i][j], ad, bp[j]);
            }
        }
        __syncthreads();
    }

    float4 bb0 = make_float4(0.f, 0.f, 0.f, 0.f), bb1 = bb0;
    if (bias) {
        bb0 = *(const float4*)&bias[bn + n0];
        bb1 = *(const float4*)&bias[bn + n0 + 4];
    }
#pragma unroll
    for (int i = 0; i < 8; i++) {
        int m = bm + m0 + i;
        float2 p0 = unpack2(acc[i][0]), p1 = unpack2(acc[i][1]);
        float2 p2 = unpack2(acc[i][2]), p3 = unpack2(acc[i][3]);
        float4 v0 = make_float4(p0.x + bb0.x, p0.y + bb0.y, p1.x + bb0.z, p1.y + bb0.w);
        float4 v1 = make_float4(p2.x + bb1.x, p2.y + bb1.y, p3.x + bb1.z, p3.y + bb1.w);
        *(float4*)&Y[(size_t)m * N + bn + n0]     = v0;
        *(float4*)&Y[(size_t)m * N + bn + n0 + 4] = v1;
    }
}

// ------------- fused LSTM step: GEMM(h @ Whq^T) + gin + elementwise -------------
// Tile: 32 batch x 128 n (= 32 units x 4 gates, interleaved). 128 threads.
// grid = (G4/128, BATCH/32) = (16, 8) = 128 blocks.
__global__ void __launch_bounds__(128) lstm_step_kernel(int s, int store_all)
{
    const int BM = 32, BN = 128, BK = 16;
    __shared__ float As[BK][BM];
    __shared__ float Bs[BK][BN];

    const float* hprev = &g_h[(s & 1) * BH];
    float*       hnext = &g_h[((s + 1) & 1) * BH];

    int bm = blockIdx.y * BM;
    int bn = blockIdx.x * BN;
    int tid = threadIdx.x;
    int tx = tid & 15;          // n group (8 n = 2 units x 4 gates)
    int ty = tid >> 4;          // m group (4 batch rows)
    int m0 = ty * 4;
    int n0 = tx * 8;

    u64 acc[4][4];
#pragma unroll
    for (int i = 0; i < 4; i++)
#pragma unroll
        for (int j = 0; j < 4; j++) acc[i][j] = 0ULL;

    for (int k0 = 0; k0 < HID; k0 += BK) {
        // A tile: 32x16 = 128 float4, one per thread
        {
            int r = tid >> 2, kq = tid & 3;
            float4 v = *(const float4*)&hprev[(size_t)(bm + r) * HID + k0 + kq * 4];
            As[kq * 4 + 0][r] = v.x; As[kq * 4 + 1][r] = v.y;
            As[kq * 4 + 2][r] = v.z; As[kq * 4 + 3][r] = v.w;
        }
        // B tile: 128x16 = 512 float4, four per thread
#pragma unroll
        for (int l = tid; l < 512; l += 128) {
            int n = l >> 2, kq = l & 3;
            float4 v = *(const float4*)&g_whq[(size_t)(bn + n) * HID + k0 + kq * 4];
            Bs[kq * 4 + 0][n] = v.x; Bs[kq * 4 + 1][n] = v.y;
            Bs[kq * 4 + 2][n] = v.z; Bs[kq * 4 + 3][n] = v.w;
        }
        __syncthreads();

#pragma unroll
        for (int k = 0; k < BK; k++) {
            float4 av = *(const float4*)&As[k][m0];
            u64 bp[4];
            bp[0] = *(const u64*)&Bs[k][n0];
            bp[1] = *(const u64*)&Bs[k][n0 + 2];
            bp[2] = *(const u64*)&Bs[k][n0 + 4];
            bp[3] = *(const u64*)&Bs[k][n0 + 6];
            float am[4] = {av.x, av.y, av.z, av.w};
#pragma unroll
            for (int i = 0; i < 4; i++) {
                u64 ad = pack2(am[i], am[i]);
#pragma unroll
                for (int j = 0; j < 4; j++) fma2(acc[i][j], ad, bp[j]);
            }
        }
        __syncthreads();
    }

    // Epilogue: add gin, apply LSTM nonlinearity, update c/h.
    int U = (bn + n0) >> 2;    // first of the 2 hidden units this thread owns
#pragma unroll
    for (int i = 0; i < 4; i++) {
        int b = bm + m0 + i;
        const float* gp = &g_gin[((size_t)s * BATCH + b) * G4 + bn + n0];
        float4 g0 = *(const float4*)&gp[0];
        float4 g1 = *(const float4*)&gp[4];
        float2 p0 = unpack2(acc[i][0]), p1 = unpack2(acc[i][1]);
        float2 p2 = unpack2(acc[i][2]), p3 = unpack2(acc[i][3]);
        float f[8] = {p0.x + g0.x, p0.y + g0.y, p1.x + g0.z, p1.y + g0.w,
                      p2.x + g1.x, p2.y + g1.y, p3.x + g1.z, p3.y + g1.w};
#pragma unroll
        for (int ul = 0; ul < 2; ul++) {
            int u = U + ul;
            float ig = sigmoidf_(f[ul * 4 + 0]);
            float fg = sigmoidf_(f[ul * 4 + 1]);
            float gg = tanhf    (f[ul * 4 + 2]);
            float og = sigmoidf_(f[ul * 4 + 3]);
            size_t idx = (size_t)b * HID + u;
            float cn = fg * g_c[idx] + ig * gg;
            float hn = og * tanhf(cn);
            g_c[idx] = cn;
            hnext[idx] = hn;
            if (store_all) g_h0all[(size_t)s * BH + idx] = hn;
        }
    }
}

// ------------- beff[n] = bcat[n] + sum_e Wicat[n][e] * b_proj[e] -------------
__global__ void __launch_bounds__(256) beff_kernel(const float* __restrict__ bproj)
{
    int n = blockIdx.x * 256 + threadIdx.x;
    if (n >= G4) return;
    float s = g_bcat[n];
    const float* w = &g_wicat[n * EMB];
    for (int e = 0; e < EMB; e++) s += w[e] * bproj[e];
    g_beff[n] = s;
}

// ------------- zero h buffer 0 and c -------------
__global__ void __launch_bounds__(256) zero_hc_kernel()
{
    int i = blockIdx.x * 256 + threadIdx.x;
    if (i < BH) { g_h[i] = 0.0f; g_c[i] = 0.0f; }
}

// =============================== launch ===============================
extern "C" void kernel_launch(void* const* d_in, const int* in_sizes, int n_in,
                              void* d_out, int out_size)
{
    const int*   X    = (const int*)  d_in[0];
    const float* C    = (const float*)d_in[1];
    const float* Wii  = (const float*)d_in[2];
    const float* Whi  = (const float*)d_in[3];
    const float* bi   = (const float*)d_in[4];
    const float* Wif  = (const float*)d_in[5];
    const float* Whf  = (const float*)d_in[6];
    const float* bf   = (const float*)d_in[7];
    const float* Wig  = (const float*)d_in[8];
    const float* Whg  = (const float*)d_in[9];
    const float* bg   = (const float*)d_in[10];
    const float* Wio  = (const float*)d_in[11];
    const float* Who  = (const float*)d_in[12];
    const float* bo   = (const float*)d_in[13];
    const float* Wp   = (const float*)d_in[14];   // [EMB, HID]
    const float* bp   = (const float*)d_in[15];   // [EMB]
    const float* Wfin = (const float*)d_in[16];   // [N_CLASS, HID]
    const float* bfin = (const float*)d_in[17];   // [N_CLASS]
    float* out = (float*)d_out;

    float *p_emb, *p_gin, *p_h0all, *p_h, *p_wicat, *p_bcat, *p_weff, *p_beff;
    cudaGetSymbolAddress((void**)&p_emb,   g_emb);
    cudaGetSymbolAddress((void**)&p_gin,   g_gin);
    cudaGetSymbolAddress((void**)&p_h0all, g_h0all);
    cudaGetSymbolAddress((void**)&p_h,     g_h);
    cudaGetSymbolAddress((void**)&p_wicat, g_wicat);
    cudaGetSymbolAddress((void**)&p_bcat,  g_bcat);
    cudaGetSymbolAddress((void**)&p_weff,  g_weff);
    cudaGetSymbolAddress((void**)&p_beff,  g_beff);

    // 1) gate-interleaved weight concat
    prep_concat_kernel<<<(G4 * HID) / 256, 256>>>(Wii, Whi, bi, Wif, Whf, bf,
                                                  Wig, Whg, bg, Wio, Who, bo);
    // 2) embedding gather
    embed_kernel<<<MB_, EMB>>>(X, C);

    // 3) Gin0 = Emb @ Wicat^T + bcat        [16384 x 2048], K=256
    gemm128_kernel<false><<<dim3(G4 / 128, MB_ / 128), 256>>>(
        p_emb, p_wicat, p_bcat, p_gin, MB_, G4, EMB);

    // 4) fold projection: Weff[n][k] = sum_e Wicat[n][e] * Wp[e][k]
    gemm128_kernel<true><<<dim3(HID / 128, G4 / 128), 256>>>(
        p_wicat, Wp, nullptr, p_weff, G4, HID, EMB);
    beff_kernel<<<G4 / 256, 256>>>(bp);

    // 5) layer-0 recurrence (fused GEMM + LSTM elementwise)
    zero_hc_kernel<<<BH / 256, 256>>>();
    for (int s = 0; s < SEQ; s++)
        lstm_step_kernel<<<dim3(G4 / 128, BATCH / 32), 128>>>(s, 1);

    // 6) Gin1 = H0all @ Weff^T + beff       [16384 x 2048], K=512
    gemm128_kernel<false><<<dim3(G4 / 128, MB_ / 128), 256>>>(
        p_h0all, p_weff, p_beff, p_gin, MB_, G4, HID);

    // 7) layer-1 recurrence
    zero_hc_kernel<<<BH / 256, 256>>>();
    for (int s = 0; s < SEQ; s++)
        lstm_step_kernel<<<dim3(G4 / 128, BATCH / 32), 128>>>(s, 0);

    // 8) logits = h_last @ Wfin^T + bfin    [256 x 32000], K=512
    //    (SEQ even -> final h in buffer 0)
    gemm128_kernel<false><<<dim3(N_CLASS / 128, BATCH / 128), 256>>>(
        p_h, Wfin, bfin, out, BATCH, N_CLASS, HID);
}